// round 4
// baseline (speedup 1.0000x reference)
#include <cuda_runtime.h>

// penalty = sum_{b,k} S[b,k] * || P[i_b] - P[j_{b,k}] ||_2
// P [500000,128] f32, i [4096] i32, j [4096,64] i32, S [4096,64] f32 -> scalar f32.
// Dynamic ticket scheduling (unit = 32 k's of one b) to collapse single-wave spread.

#define B_TOTAL 4096
#define K_NEIGH 64
#define D_DIM   128
#define UNITS   (B_TOTAL * 2)   // 8192 units of 32 gathers
#define WIN     8
#define FULL    0xFFFFFFFFu

__device__ int g_ticket;

__global__ void zero_out_kernel(float* out) { *out = 0.0f; g_ticket = 0; }

__global__ __launch_bounds__(128, 8)
void custom_loss_kernel(const float* __restrict__ P,
                        const int*   __restrict__ i_idx,
                        const int*   __restrict__ j_idx,
                        const float* __restrict__ S,
                        float* __restrict__ out) {
    const int lane = threadIdx.x & 31;

    float acc = 0.0f;

    int unit;
    if (lane == 0) unit = atomicAdd(&g_ticket, 1);
    unit = __shfl_sync(FULL, unit, 0);

    while (unit < UNITS) {
        const int b     = unit >> 1;
        const int kbase = (unit & 1) << 5;            // 0 or 32

        // Per-unit setup: Pi row slice, 32 indices + 32 scales in registers.
        const int irow = __ldg(i_idx + b);
        const float4 pi = __ldg(reinterpret_cast<const float4*>(P + (unsigned)irow * D_DIM) + lane);
        const int   jreg = __ldg(j_idx + b * K_NEIGH + kbase + lane);
        const float sreg = __ldg(S     + b * K_NEIGH + kbase + lane);

        // Prologue: fill the gather window (8 independent 512B row reads).
        float4 pj[WIN];
        #pragma unroll
        for (int m = 0; m < WIN; m++) {
            unsigned jr = (unsigned)__shfl_sync(FULL, jreg, m);
            pj[m] = __ldg(reinterpret_cast<const float4*>(P + jr * D_DIM) + lane);
        }

        // Overlap the next ticket pull with this unit's processing.
        int nu;
        if (lane == 0) nu = atomicAdd(&g_ticket, 1);

        #pragma unroll
        for (int k0 = 0; k0 < 32; k0 += WIN) {
            #pragma unroll
            for (int m = 0; m < WIN; m++) {
                const int k = k0 + m;
                float dx = pi.x - pj[m].x;
                float dy = pi.y - pj[m].y;
                float dz = pi.z - pj[m].z;
                float dw = pi.w - pj[m].w;
                if (k + WIN < 32) {
                    unsigned jr = (unsigned)__shfl_sync(FULL, jreg, k + WIN);
                    pj[m] = __ldg(reinterpret_cast<const float4*>(P + jr * D_DIM) + lane);
                }
                float sq = dx * dx + dy * dy + dz * dz + dw * dw;
                #pragma unroll
                for (int off = 16; off > 0; off >>= 1)
                    sq += __shfl_xor_sync(FULL, sq, off);
                // All lanes hold the full norm^2; lane k owns S[k] -> local accumulate.
                if (lane == k)
                    acc += sqrtf(sq) * sreg;
            }
        }

        unit = __shfl_sync(FULL, nu, 0);
    }

    // Warp-reduce local accumulators, one atomic per warp.
    #pragma unroll
    for (int off = 16; off > 0; off >>= 1)
        acc += __shfl_xor_sync(FULL, acc, off);
    if (lane == 0) atomicAdd(out, acc);
}

extern "C" void kernel_launch(void* const* d_in, const int* in_sizes, int n_in,
                              void* d_out, int out_size) {
    const float* P  = (const float*)d_in[0];
    const int*   ii = (const int*)  d_in[1];
    const int*   jj = (const int*)  d_in[2];
    const float* S  = (const float*)d_in[3];
    float* out = (float*)d_out;

    zero_out_kernel<<<1, 1>>>(out);
    custom_loss_kernel<<<1024, 128>>>(P, ii, jj, S, out);
}

// round 5
// speedup vs baseline: 1.0790x; 1.0790x over previous
#include <cuda_runtime.h>

// penalty = sum_{b,k} S[b,k] * || P[i_b] - P[j_{b,k}] ||_2
// P [500000,128] f32, i [4096] i32, j [4096,64] i32, S [4096,64] f32 -> scalar f32.
// One warp per b (R3 structure), rolling 12-deep gather window, fully unrolled.

#define B_TOTAL 4096
#define K_NEIGH 64
#define D_DIM   128
#define WPB     4          // warps per block
#define WIN     12         // rolling gather window per warp
#define FULL    0xFFFFFFFFu

__global__ void zero_out_kernel(float* out) { *out = 0.0f; }

__global__ __launch_bounds__(WPB * 32, 6)
void custom_loss_kernel(const float* __restrict__ P,
                        const int*   __restrict__ i_idx,
                        const int*   __restrict__ j_idx,
                        const float* __restrict__ S,
                        float* __restrict__ out) {
    const int lane = threadIdx.x & 31;
    const int w    = threadIdx.x >> 5;
    const int b    = blockIdx.x * WPB + w;

    __shared__ int   sJ[WPB][K_NEIGH];
    __shared__ float sS[WPB][K_NEIGH];

    // Warp-private coalesced staging; no block barrier.
    sJ[w][lane]      = j_idx[b * K_NEIGH + lane];
    sJ[w][32 + lane] = j_idx[b * K_NEIGH + 32 + lane];
    sS[w][lane]      = S[b * K_NEIGH + lane];
    sS[w][32 + lane] = S[b * K_NEIGH + 32 + lane];
    const unsigned irow = (unsigned)i_idx[b];
    const float4 pi = __ldg(reinterpret_cast<const float4*>(P + irow * (unsigned)D_DIM) + lane);
    __syncwarp();

    // Prologue: fill the 12-slot gather window.
    float4 pj[WIN];
    #pragma unroll
    for (int m = 0; m < WIN; m++) {
        unsigned jr = (unsigned)sJ[w][m];
        pj[m] = __ldg(reinterpret_cast<const float4*>(P + jr * (unsigned)D_DIM) + lane);
    }

    float acc = 0.0f;
    #pragma unroll
    for (int k = 0; k < K_NEIGH; k++) {
        const int m = k % WIN;            // compile-time after full unroll
        float dx = pi.x - pj[m].x;
        float dy = pi.y - pj[m].y;
        float dz = pi.z - pj[m].z;
        float dw = pi.w - pj[m].w;
        // Refill slot m immediately so ~WIN loads stay in flight.
        if (k + WIN < K_NEIGH) {
            unsigned jr = (unsigned)sJ[w][k + WIN];
            pj[m] = __ldg(reinterpret_cast<const float4*>(P + jr * (unsigned)D_DIM) + lane);
        }
        float sq = dx * dx + dy * dy + dz * dz + dw * dw;
        #pragma unroll
        for (int off = 16; off > 0; off >>= 1)
            sq += __shfl_xor_sync(FULL, sq, off);
        if (lane == 0)
            acc += sqrtf(sq) * sS[w][k];
    }

    if (lane == 0) atomicAdd(out, acc);
}

extern "C" void kernel_launch(void* const* d_in, const int* in_sizes, int n_in,
                              void* d_out, int out_size) {
    const float* P  = (const float*)d_in[0];
    const int*   ii = (const int*)  d_in[1];
    const int*   jj = (const int*)  d_in[2];
    const float* S  = (const float*)d_in[3];
    float* out = (float*)d_out;

    zero_out_kernel<<<1, 1>>>(out);
    custom_loss_kernel<<<B_TOTAL / WPB, WPB * 32>>>(P, ii, jj, S, out);
}

// round 6
// speedup vs baseline: 1.1686x; 1.0830x over previous
#include <cuda_runtime.h>

// penalty = sum_{b,k} S[b,k] * || P[i_b] - P[j_{b,k}] ||_2
// P [500000,128] f32, i [4096] i32, j [4096,64] i32, S [4096,64] f32 -> scalar f32.
// One warp per b. 8 lanes per row / 4 rows per warp-step: 3 shfl per 4 rows
// instead of 5 shfl per row; rolling 2-group-set window (8 rows in flight).

#define B_TOTAL 4096
#define K_NEIGH 64
#define D_DIM   128
#define WPB     4
#define NGS     (K_NEIGH / 4)   // 16 group-sets of 4 rows
#define GWIN    2               // group-sets in flight (8 rows)
#define FULL    0xFFFFFFFFu

__global__ void zero_out_kernel(float* out) { *out = 0.0f; }

__global__ __launch_bounds__(WPB * 32, 6)
void custom_loss_kernel(const float* __restrict__ P,
                        const int*   __restrict__ i_idx,
                        const int*   __restrict__ j_idx,
                        const float* __restrict__ S,
                        float* __restrict__ out) {
    const int lane = threadIdx.x & 31;
    const int w    = threadIdx.x >> 5;
    const int b    = blockIdx.x * WPB + w;
    const int g    = lane >> 3;      // row group within warp-step (0..3)
    const int sub  = lane & 7;       // lane within row group

    __shared__ int   sJ[WPB][K_NEIGH];
    __shared__ float sS[WPB][K_NEIGH];

    // Warp-private coalesced staging.
    sJ[w][lane]      = j_idx[b * K_NEIGH + lane];
    sJ[w][32 + lane] = j_idx[b * K_NEIGH + 32 + lane];
    sS[w][lane]      = S[b * K_NEIGH + lane];
    sS[w][32 + lane] = S[b * K_NEIGH + 32 + lane];
    __syncwarp();

    // Pi slots for this lane: float4 index sub + 8*it  (same for all 4 groups).
    const unsigned irow = (unsigned)i_idx[b];
    const float4* PiRow = reinterpret_cast<const float4*>(P + irow * (unsigned)D_DIM);
    float4 pi4[4];
    #pragma unroll
    for (int it = 0; it < 4; it++)
        pi4[it] = __ldg(PiRow + sub + 8 * it);

    // Prologue: fill GWIN group-sets (each = this lane's 4 float4 of its group's row).
    float4 pj[GWIN][4];
    #pragma unroll
    for (int q = 0; q < GWIN; q++) {
        unsigned jr = (unsigned)sJ[w][4 * q + g];
        const float4* row = reinterpret_cast<const float4*>(P + jr * (unsigned)D_DIM);
        #pragma unroll
        for (int it = 0; it < 4; it++)
            pj[q][it] = __ldg(row + sub + 8 * it);
    }

    float acc = 0.0f;
    #pragma unroll
    for (int gs = 0; gs < NGS; gs++) {
        const int q = gs % GWIN;     // compile-time after unroll

        // Per-lane partial squared distance over its 16 elements.
        float sq = 0.0f;
        #pragma unroll
        for (int it = 0; it < 4; it++) {
            float dx = pi4[it].x - pj[q][it].x;
            float dy = pi4[it].y - pj[q][it].y;
            float dz = pi4[it].z - pj[q][it].z;
            float dw = pi4[it].w - pj[q][it].w;
            sq += dx * dx + dy * dy + dz * dz + dw * dw;
        }

        // Refill slot q immediately (keep 8 rows in flight).
        if (gs + GWIN < NGS) {
            unsigned jr = (unsigned)sJ[w][4 * (gs + GWIN) + g];
            const float4* row = reinterpret_cast<const float4*>(P + jr * (unsigned)D_DIM);
            #pragma unroll
            for (int it = 0; it < 4; it++)
                pj[q][it] = __ldg(row + sub + 8 * it);
        }

        // Reduce within each 8-lane group (handles 4 rows in 3 shuffles).
        sq += __shfl_xor_sync(FULL, sq, 1);
        sq += __shfl_xor_sync(FULL, sq, 2);
        sq += __shfl_xor_sync(FULL, sq, 4);

        if (sub == 0)
            acc += sqrtf(sq) * sS[w][4 * gs + g];
    }

    // Final warp reduce (only lanes 0,8,16,24 hold data) + one atomic per warp.
    acc += __shfl_xor_sync(FULL, acc, 8);
    acc += __shfl_xor_sync(FULL, acc, 16);
    if (lane == 0) atomicAdd(out, acc);
}

extern "C" void kernel_launch(void* const* d_in, const int* in_sizes, int n_in,
                              void* d_out, int out_size) {
    const float* P  = (const float*)d_in[0];
    const int*   ii = (const int*)  d_in[1];
    const int*   jj = (const int*)  d_in[2];
    const float* S  = (const float*)d_in[3];
    float* out = (float*)d_out;

    zero_out_kernel<<<1, 1>>>(out);
    custom_loss_kernel<<<B_TOTAL / WPB, WPB * 32>>>(P, ii, jj, S, out);
}

// round 7
// speedup vs baseline: 1.1701x; 1.0013x over previous
#include <cuda_runtime.h>

// penalty = sum_{b,k} S[b,k] * || P[i_b] - P[j_{b,k}] ||_2
// P [500000,128] f32, i [4096] i32, j [4096,64] i32, S [4096,64] f32 -> scalar f32.
// Unit = 32 k's of one b per warp (8192 units, ~2 waves for tail backfill).
// 8 lanes per row / 4 rows per step, 3 shfl per 4 rows, 8 rows in flight.

#define B_TOTAL 4096
#define K_NEIGH 64
#define D_DIM   128
#define WPB     4
#define KPU     32              // k's per unit (warp)
#define NGS     (KPU / 4)       // 8 group-sets of 4 rows per unit
#define GWIN    2               // group-sets in flight (8 rows)
#define FULL    0xFFFFFFFFu

__global__ void zero_out_kernel(float* out) { *out = 0.0f; }

__global__ __launch_bounds__(WPB * 32, 6)
void custom_loss_kernel(const float* __restrict__ P,
                        const int*   __restrict__ i_idx,
                        const int*   __restrict__ j_idx,
                        const float* __restrict__ S,
                        float* __restrict__ out) {
    const int lane = threadIdx.x & 31;
    const int w    = threadIdx.x >> 5;
    const int unit = blockIdx.x * WPB + w;          // 0 .. 8191
    const int b    = unit >> 1;
    const int koff = (unit & 1) << 5;               // 0 or 32
    const int g    = lane >> 3;                     // row group (0..3)
    const int sub  = lane & 7;                      // lane within group

    __shared__ int   sJ[WPB][KPU];
    __shared__ float sS[WPB][KPU];

    // Warp-private coalesced staging (32 j's + 32 S's for this unit).
    sJ[w][lane] = j_idx[b * K_NEIGH + koff + lane];
    sS[w][lane] = S[b * K_NEIGH + koff + lane];
    __syncwarp();

    // Pi slots for this lane (independent of group).
    const unsigned irow = (unsigned)i_idx[b];
    const float4* PiRow = reinterpret_cast<const float4*>(P + irow * (unsigned)D_DIM);
    float4 pi4[4];
    #pragma unroll
    for (int it = 0; it < 4; it++)
        pi4[it] = __ldg(PiRow + sub + 8 * it);

    // Prologue: fill GWIN group-sets.
    float4 pj[GWIN][4];
    #pragma unroll
    for (int q = 0; q < GWIN; q++) {
        unsigned jr = (unsigned)sJ[w][4 * q + g];
        const float4* row = reinterpret_cast<const float4*>(P + jr * (unsigned)D_DIM);
        #pragma unroll
        for (int it = 0; it < 4; it++)
            pj[q][it] = __ldg(row + sub + 8 * it);
    }

    float acc = 0.0f;
    #pragma unroll
    for (int gs = 0; gs < NGS; gs++) {
        const int q = gs % GWIN;    // compile-time after full unroll

        float sq = 0.0f;
        #pragma unroll
        for (int it = 0; it < 4; it++) {
            float dx = pi4[it].x - pj[q][it].x;
            float dy = pi4[it].y - pj[q][it].y;
            float dz = pi4[it].z - pj[q][it].z;
            float dw = pi4[it].w - pj[q][it].w;
            sq += dx * dx + dy * dy + dz * dz + dw * dw;
        }

        // Refill slot q immediately (keeps 8 rows in flight).
        if (gs + GWIN < NGS) {
            unsigned jr = (unsigned)sJ[w][4 * (gs + GWIN) + g];
            const float4* row = reinterpret_cast<const float4*>(P + jr * (unsigned)D_DIM);
            #pragma unroll
            for (int it = 0; it < 4; it++)
                pj[q][it] = __ldg(row + sub + 8 * it);
        }

        // Reduce within each 8-lane group (4 rows per 3 shuffles).
        sq += __shfl_xor_sync(FULL, sq, 1);
        sq += __shfl_xor_sync(FULL, sq, 2);
        sq += __shfl_xor_sync(FULL, sq, 4);

        if (sub == 0)
            acc += sqrtf(sq) * sS[w][4 * gs + g];
    }

    // Lanes 0,8,16,24 hold partials; reduce and emit one atomic per warp.
    acc += __shfl_xor_sync(FULL, acc, 8);
    acc += __shfl_xor_sync(FULL, acc, 16);
    if (lane == 0) atomicAdd(out, acc);
}

extern "C" void kernel_launch(void* const* d_in, const int* in_sizes, int n_in,
                              void* d_out, int out_size) {
    const float* P  = (const float*)d_in[0];
    const int*   ii = (const int*)  d_in[1];
    const int*   jj = (const int*)  d_in[2];
    const float* S  = (const float*)d_in[3];
    float* out = (float*)d_out;

    zero_out_kernel<<<1, 1>>>(out);
    // 8192 units / 4 warps per block = 2048 blocks (~2 waves).
    custom_loss_kernel<<<(B_TOTAL * 2) / WPB, WPB * 32>>>(P, ii, jj, S, out);
}